// round 1
// baseline (speedup 1.0000x reference)
#include <cuda_runtime.h>
#include <math.h>

// ---------------------------------------------------------------------------
// Problem constants
// ---------------------------------------------------------------------------
#define BB   16
#define NN   512
#define DIM  256
#define NH   8
#define HD   32
#define ROWS (BB*NN)          // 8192
#define MAXD 128
#define NG   32

// scratch layout (floats)
#define OFF_BIAS 0                         // [B,H,N,N] = 33554432
#define OFF_H    33554432                  // ln1 out   [8192,256]
#define OFF_QKV  (OFF_H    + 2097152)      // [8192,768]
#define OFF_CTX  (OFF_QKV  + 6291456)      // [8192,256]
#define OFF_HATT (OFF_CTX  + 2097152)      // [8192,256]
#define OFF_H2   (OFF_HATT + 2097152)      // [8192,256]
#define OFF_F1   (OFF_H2   + 2097152)      // [8192,1024]
#define SCRATCH_FLOATS (OFF_F1 + 8388608)  // 56623104

__device__ float g_scratch[SCRATCH_FLOATS];

// ---------------------------------------------------------------------------
// LayerNorm: one block per row (256 threads, 1 elem/thread)
// ---------------------------------------------------------------------------
__global__ void ln_kernel(const float* __restrict__ x,
                          const float* __restrict__ g,
                          const float* __restrict__ be,
                          float* __restrict__ out) {
    int row = blockIdx.x;
    int t   = threadIdx.x;
    float v = x[row * DIM + t];

    float s = v, sq = v * v;
    #pragma unroll
    for (int off = 16; off; off >>= 1) {
        s  += __shfl_xor_sync(0xffffffffu, s,  off);
        sq += __shfl_xor_sync(0xffffffffu, sq, off);
    }
    __shared__ float rs[8], rq[8];
    int warp = t >> 5, lane = t & 31;
    if (lane == 0) { rs[warp] = s; rq[warp] = sq; }
    __syncthreads();
    float ts = 0.f, tq = 0.f;
    #pragma unroll
    for (int w = 0; w < 8; w++) { ts += rs[w]; tq += rq[w]; }

    float mean = ts * (1.0f / DIM);
    float var  = tq * (1.0f / DIM) - mean * mean;
    float inv  = rsqrtf(var + 1e-5f);
    out[row * DIM + t] = (v - mean) * inv * g[t] + be[t];
}

// ---------------------------------------------------------------------------
// Bias kernel: bias[b,h,q,k] = dist_emb[clamp(dm)][h] + sum_g rbf_g*rbf_w[h,g] + rbf_b[h]
// one block per (b,q), threads over k
// ---------------------------------------------------------------------------
__global__ void bias_kernel(const int*   __restrict__ dm,
                            const float* __restrict__ d3,
                            const float* __restrict__ dist_emb,
                            const float* __restrict__ rbf_w,
                            const float* __restrict__ rbf_b,
                            float* __restrict__ bias) {
    int bq = blockIdx.x;            // 0..8191
    int b  = bq >> 9;
    int q  = bq & 511;
    int t  = threadIdx.x;

    __shared__ float w_s[NH * NG];
    __shared__ float b_s[NH];
    __shared__ float emb_s[MAXD * NH];
    if (t < NH * NG) w_s[t] = rbf_w[t];
    if (t < NH)      b_s[t] = rbf_b[t];
    for (int i = t; i < MAXD * NH; i += 256) emb_s[i] = dist_emb[i];
    __syncthreads();

    const float step  = 20.0f / 31.0f;
    const float coeff = -0.5f / (step * step);
    size_t base = (size_t)bq * NN;

    for (int k = t; k < NN; k += 256) {
        float dd = d3[base + k];
        int   di = dm[base + k];
        di = min(max(di, 0), MAXD - 1);

        float r[NG];
        #pragma unroll
        for (int gg = 0; gg < NG; gg++) {
            float diff = dd - (float)gg * step;
            r[gg] = __expf(coeff * diff * diff);
        }
        #pragma unroll
        for (int h = 0; h < NH; h++) {
            float acc = b_s[h] + emb_s[di * NH + h];
            #pragma unroll
            for (int gg = 0; gg < NG; gg++) acc += r[gg] * w_s[h * NG + gg];
            bias[(((size_t)(b * NH + h) * NN + q) * NN) + k] = acc;
        }
    }
}

// ---------------------------------------------------------------------------
// Flash attention: block = (q-tile 64, head, batch); 256 threads
//   scores(64x64) += bias, online softmax, ctx accumulated in registers
//   writes ctx in [B,N,H*HD] layout (ready for out_proj)
// ---------------------------------------------------------------------------
__global__ void attn_kernel(const float* __restrict__ qkv,
                            const float* __restrict__ bias,
                            float* __restrict__ ctx) {
    const int qt = blockIdx.x;   // 0..7
    const int h  = blockIdx.y;   // 0..7
    const int b  = blockIdx.z;   // 0..15
    const int q0 = qt * 64;
    const int t  = threadIdx.x;

    __shared__ float Qs[64][33];
    __shared__ float Ks[64][33];
    __shared__ float Vs[64][32];
    __shared__ float S [64][65];
    __shared__ float m_row[64], l_row[64], f_row[64];

    const int d  = t & 31;
    const int iw = t >> 5;                 // warp id 0..7
    const int lane = t & 31;

    // load Q tile (coalesced: one row of 32 floats per warp)
    #pragma unroll
    for (int j = 0; j < 8; j++) {
        int i = iw + j * 8;
        Qs[i][d] = qkv[(size_t)(b * NN + q0 + i) * 768 + h * HD + d];
    }
    if (t < 64) { m_row[t] = -1e30f; l_row[t] = 0.f; f_row[t] = 0.f; }

    // score mapping: 4x4 micro-tile
    const int si = (t >> 4) * 4;
    const int sj = (t & 15) * 4;
    // PV mapping: 4 q-rows x 2 d
    const int qp = (t >> 4) * 4;
    const int d2 = (t & 15) * 2;
    float acc[4][2] = {};
    const float scale = 0.17677669529663687f; // 1/sqrt(32)

    for (int kt = 0; kt < 8; kt++) {
        int k0 = kt * 64;
        __syncthreads();  // protect S/Vs from previous PV before overwrite
        #pragma unroll
        for (int j = 0; j < 8; j++) {
            int i = iw + j * 8;
            size_t base = (size_t)(b * NN + k0 + i) * 768 + h * HD + d;
            Ks[i][d] = qkv[base + 256];
            Vs[i][d] = qkv[base + 512];
        }
        __syncthreads();

        // S[si..si+3][sj..sj+3]
        float s4[4][4] = {};
        #pragma unroll
        for (int dd = 0; dd < 32; dd++) {
            float a0 = Qs[si + 0][dd], a1 = Qs[si + 1][dd];
            float a2 = Qs[si + 2][dd], a3 = Qs[si + 3][dd];
            float b0 = Ks[sj + 0][dd], b1 = Ks[sj + 1][dd];
            float b2 = Ks[sj + 2][dd], b3 = Ks[sj + 3][dd];
            s4[0][0] += a0 * b0; s4[0][1] += a0 * b1; s4[0][2] += a0 * b2; s4[0][3] += a0 * b3;
            s4[1][0] += a1 * b0; s4[1][1] += a1 * b1; s4[1][2] += a1 * b2; s4[1][3] += a1 * b3;
            s4[2][0] += a2 * b0; s4[2][1] += a2 * b1; s4[2][2] += a2 * b2; s4[2][3] += a2 * b3;
            s4[3][0] += a3 * b0; s4[3][1] += a3 * b1; s4[3][2] += a3 * b2; s4[3][3] += a3 * b3;
        }
        #pragma unroll
        for (int r = 0; r < 4; r++) {
            const float4 bv = *(const float4*)&bias[
                ((size_t)(b * NH + h) * NN + (q0 + si + r)) * NN + k0 + sj];
            S[si + r][sj + 0] = s4[r][0] * scale + bv.x;
            S[si + r][sj + 1] = s4[r][1] * scale + bv.y;
            S[si + r][sj + 2] = s4[r][2] * scale + bv.z;
            S[si + r][sj + 3] = s4[r][3] * scale + bv.w;
        }
        __syncthreads();

        // online softmax: warp iw owns rows iw*8..iw*8+7
        #pragma unroll
        for (int rr = 0; rr < 8; rr++) {
            int row = iw * 8 + rr;
            float v0 = S[row][lane * 2], v1 = S[row][lane * 2 + 1];
            float mx = fmaxf(v0, v1);
            #pragma unroll
            for (int off = 16; off; off >>= 1)
                mx = fmaxf(mx, __shfl_xor_sync(0xffffffffu, mx, off));
            float mo = m_row[row];
            float mn = fmaxf(mo, mx);
            float p0 = __expf(v0 - mn), p1 = __expf(v1 - mn);
            S[row][lane * 2] = p0; S[row][lane * 2 + 1] = p1;
            float ls = p0 + p1;
            #pragma unroll
            for (int off = 16; off; off >>= 1)
                ls += __shfl_xor_sync(0xffffffffu, ls, off);
            if (lane == 0) {
                float f = __expf(mo - mn);
                m_row[row] = mn;
                l_row[row] = l_row[row] * f + ls;
                f_row[row] = f;
            }
        }
        __syncthreads();

        // rescale + accumulate P@V
        #pragma unroll
        for (int r = 0; r < 4; r++) {
            float f = f_row[qp + r];
            acc[r][0] *= f; acc[r][1] *= f;
        }
        for (int k = 0; k < 64; k++) {
            float2 vv = *(const float2*)&Vs[k][d2];
            #pragma unroll
            for (int r = 0; r < 4; r++) {
                float p = S[qp + r][k];
                acc[r][0] += p * vv.x;
                acc[r][1] += p * vv.y;
            }
        }
    }

    // normalize + write ctx[b, n, h*32 + d]
    #pragma unroll
    for (int r = 0; r < 4; r++) {
        int row = qp + r;
        float inv = 1.0f / l_row[row];
        float2 o;
        o.x = acc[r][0] * inv;
        o.y = acc[r][1] * inv;
        *(float2*)&ctx[(size_t)(b * NN + q0 + row) * DIM + h * HD + d2] = o;
    }
}

// ---------------------------------------------------------------------------
// SGEMM: C[M,Nn] = A[M,K] @ B[Nn,K]^T + bias (+gelu)(+res)
// BM=128 BN=64 BK=16, 256 threads, 8x4 micro-tile. M,Nn,K all tile-divisible.
// ---------------------------------------------------------------------------
template<bool GELU, bool RES>
__global__ void sgemm_nt(const float* __restrict__ A,
                         const float* __restrict__ Bw,
                         const float* __restrict__ bias,
                         const float* __restrict__ res,
                         float* __restrict__ C,
                         int Nn, int K) {
    __shared__ float As[16][132];
    __shared__ float Bs[16][68];

    const int t  = threadIdx.x;
    const int bm = blockIdx.x * 128;
    const int bn = blockIdx.y * 64;
    const int tm = (t >> 4) << 3;   // 0..120
    const int tn = (t & 15) << 2;   // 0..60

    float acc[8][4] = {};

    for (int k0 = 0; k0 < K; k0 += 16) {
        // A tile: 128x16 = 512 float4, 2 per thread
        #pragma unroll
        for (int r = 0; r < 2; r++) {
            int idx = t + r * 256;
            int row = idx >> 2;
            int c4  = (idx & 3) << 2;
            float4 v = *(const float4*)&A[(size_t)(bm + row) * K + k0 + c4];
            As[c4 + 0][row] = v.x; As[c4 + 1][row] = v.y;
            As[c4 + 2][row] = v.z; As[c4 + 3][row] = v.w;
        }
        // B tile: 64x16 = 256 float4, 1 per thread
        {
            int row = t >> 2;
            int c4  = (t & 3) << 2;
            float4 v = *(const float4*)&Bw[(size_t)(bn + row) * K + k0 + c4];
            Bs[c4 + 0][row] = v.x; Bs[c4 + 1][row] = v.y;
            Bs[c4 + 2][row] = v.z; Bs[c4 + 3][row] = v.w;
        }
        __syncthreads();

        #pragma unroll
        for (int k = 0; k < 16; k++) {
            float4 a0 = *(const float4*)&As[k][tm];
            float4 a1 = *(const float4*)&As[k][tm + 4];
            float4 bf = *(const float4*)&Bs[k][tn];
            float av[8] = {a0.x, a0.y, a0.z, a0.w, a1.x, a1.y, a1.z, a1.w};
            float bv[4] = {bf.x, bf.y, bf.z, bf.w};
            #pragma unroll
            for (int i = 0; i < 8; i++)
                #pragma unroll
                for (int j = 0; j < 4; j++)
                    acc[i][j] += av[i] * bv[j];
        }
        __syncthreads();
    }

    float bb[4];
    #pragma unroll
    for (int j = 0; j < 4; j++) bb[j] = bias[bn + tn + j];

    #pragma unroll
    for (int i = 0; i < 8; i++) {
        int row = bm + tm + i;
        float4 o;
        float v[4];
        #pragma unroll
        for (int j = 0; j < 4; j++) {
            float x = acc[i][j] + bb[j];
            if (GELU) x = 0.5f * x * (1.0f + erff(x * 0.70710678118654752f));
            v[j] = x;
        }
        if (RES) {
            float4 rr = *(const float4*)&res[(size_t)row * Nn + bn + tn];
            v[0] += rr.x; v[1] += rr.y; v[2] += rr.z; v[3] += rr.w;
        }
        o.x = v[0]; o.y = v[1]; o.z = v[2]; o.w = v[3];
        *(float4*)&C[(size_t)row * Nn + bn + tn] = o;
    }
}

// ---------------------------------------------------------------------------
// launch
// ---------------------------------------------------------------------------
extern "C" void kernel_launch(void* const* d_in, const int* in_sizes, int n_in,
                              void* d_out, int out_size) {
    const float* x    = (const float*)d_in[0];
    // d_in[1] = batch (unused: equal-size graphs)
    const int*   dm   = (const int*)  d_in[2];
    const float* d3   = (const float*)d_in[3];
    const float* n1g  = (const float*)d_in[4];
    const float* n1b  = (const float*)d_in[5];
    const float* ipw  = (const float*)d_in[6];
    const float* ipb  = (const float*)d_in[7];
    const float* opw  = (const float*)d_in[8];
    const float* opb  = (const float*)d_in[9];
    const float* demb = (const float*)d_in[10];
    const float* rbfw = (const float*)d_in[11];
    const float* rbfb = (const float*)d_in[12];
    const float* n2g  = (const float*)d_in[13];
    const float* n2b  = (const float*)d_in[14];
    const float* w1   = (const float*)d_in[15];
    const float* b1   = (const float*)d_in[16];
    const float* w2   = (const float*)d_in[17];
    const float* b2   = (const float*)d_in[18];
    float* out = (float*)d_out;

    float* scratch = nullptr;
    cudaGetSymbolAddress((void**)&scratch, g_scratch);
    float* bias = scratch + OFF_BIAS;
    float* hs   = scratch + OFF_H;
    float* qkv  = scratch + OFF_QKV;
    float* ctx  = scratch + OFF_CTX;
    float* hatt = scratch + OFF_HATT;
    float* h2   = scratch + OFF_H2;
    float* f1   = scratch + OFF_F1;

    // 1. h = LN1(x)
    ln_kernel<<<ROWS, 256>>>(x, n1g, n1b, hs);
    // 2. qkv = h @ in_proj_w^T + b
    sgemm_nt<false, false><<<dim3(ROWS / 128, 768 / 64), 256>>>(hs, ipw, ipb, nullptr, qkv, 768, 256);
    // 3. bias[b,h,q,k]
    bias_kernel<<<ROWS, 256>>>(dm, d3, demb, rbfw, rbfb, bias);
    // 4. attention -> ctx [B,N,DIM]
    attn_kernel<<<dim3(NN / 64, NH, BB), 256>>>(qkv, bias, ctx);
    // 5. hatt = ctx @ out_proj^T + b + h
    sgemm_nt<false, true><<<dim3(ROWS / 128, 256 / 64), 256>>>(ctx, opw, opb, hs, hatt, 256, 256);
    // 6. h2 = LN2(hatt)
    ln_kernel<<<ROWS, 256>>>(hatt, n2g, n2b, h2);
    // 7. f1 = gelu(h2 @ w1^T + b1)
    sgemm_nt<true, false><<<dim3(ROWS / 128, 1024 / 64), 256>>>(h2, w1, b1, nullptr, f1, 1024, 256);
    // 8. out = f1 @ w2^T + b2 + hatt
    sgemm_nt<false, true><<<dim3(ROWS / 128, 256 / 64), 256>>>(f1, w2, b2, hatt, out, 256, 1024);
}

// round 2
// speedup vs baseline: 1.7378x; 1.7378x over previous
#include <cuda_runtime.h>
#include <cuda_fp16.h>
#include <math.h>
#include <stdint.h>

// ---------------------------------------------------------------------------
// Problem constants
// ---------------------------------------------------------------------------
#define BB   16
#define NN   512
#define DIM  256
#define NH   8
#define HD   32
#define ROWS (BB*NN)          // 8192
#define MAXD 128
#define NG   32

// scratch layout (floats). bias is __half (33554432 halves = 16777216 floats)
#define OFF_BIAS 0
#define OFF_H    16777216                  // ln1 out   [8192,256]
#define OFF_QKV  (OFF_H    + 2097152)      // [8192,768]
#define OFF_CTX  (OFF_QKV  + 6291456)      // [8192,256]
#define OFF_HATT (OFF_CTX  + 2097152)      // [8192,256]
#define OFF_H2   (OFF_HATT + 2097152)      // [8192,256]
#define OFF_F1   (OFF_H2   + 2097152)      // [8192,1024]
#define SCRATCH_FLOATS (OFF_F1 + 8388608)

__device__ float g_scratch[SCRATCH_FLOATS];

// ---------------------------------------------------------------------------
// helpers
// ---------------------------------------------------------------------------
__device__ __forceinline__ uint32_t f2tf32(float x) {
    uint32_t r;
    asm("cvt.rna.tf32.f32 %0, %1;" : "=r"(r) : "f"(x));
    return r;
}

__device__ __forceinline__ void cp16(void* s, const void* g) {
    unsigned sa = (unsigned)__cvta_generic_to_shared(s);
    asm volatile("cp.async.cg.shared.global [%0], [%1], 16;" :: "r"(sa), "l"(g));
}
#define CP_COMMIT() asm volatile("cp.async.commit_group;")

__device__ __forceinline__ void mma_tf32(float& d0, float& d1, float& d2, float& d3,
                                         uint32_t a0, uint32_t a1, uint32_t a2, uint32_t a3,
                                         uint32_t b0, uint32_t b1) {
    asm volatile(
        "mma.sync.aligned.m16n8k8.row.col.f32.tf32.tf32.f32 "
        "{%0,%1,%2,%3}, {%4,%5,%6,%7}, {%8,%9}, {%0,%1,%2,%3};\n"
        : "+f"(d0), "+f"(d1), "+f"(d2), "+f"(d3)
        : "r"(a0), "r"(a1), "r"(a2), "r"(a3), "r"(b0), "r"(b1));
}

// ---------------------------------------------------------------------------
// LayerNorm: one block per row (256 threads, 1 elem/thread)
// ---------------------------------------------------------------------------
__global__ void ln_kernel(const float* __restrict__ x,
                          const float* __restrict__ g,
                          const float* __restrict__ be,
                          float* __restrict__ out) {
    int row = blockIdx.x;
    int t   = threadIdx.x;
    float v = x[row * DIM + t];

    float s = v, sq = v * v;
    #pragma unroll
    for (int off = 16; off; off >>= 1) {
        s  += __shfl_xor_sync(0xffffffffu, s,  off);
        sq += __shfl_xor_sync(0xffffffffu, sq, off);
    }
    __shared__ float rs[8], rq[8];
    int warp = t >> 5, lane = t & 31;
    if (lane == 0) { rs[warp] = s; rq[warp] = sq; }
    __syncthreads();
    float ts = 0.f, tq = 0.f;
    #pragma unroll
    for (int w = 0; w < 8; w++) { ts += rs[w]; tq += rq[w]; }

    float mean = ts * (1.0f / DIM);
    float var  = tq * (1.0f / DIM) - mean * mean;
    float inv  = rsqrtf(var + 1e-5f);
    out[row * DIM + t] = (v - mean) * inv * g[t] + be[t];
}

// ---------------------------------------------------------------------------
// Bias kernel -> __half bias[b,h,q,k]
// one block per (b,q), thread t handles k = 2t, 2t+1
// ---------------------------------------------------------------------------
__global__ void bias_kernel(const int*   __restrict__ dm,
                            const float* __restrict__ d3,
                            const float* __restrict__ dist_emb,
                            const float* __restrict__ rbf_w,
                            const float* __restrict__ rbf_b,
                            __half* __restrict__ bias) {
    int bq = blockIdx.x;            // 0..8191
    int b  = bq >> 9;
    int q  = bq & 511;
    int t  = threadIdx.x;

    __shared__ float w_s[NH * NG];
    __shared__ float b_s[NH];
    __shared__ float emb_s[MAXD * NH];
    if (t < NH * NG) w_s[t] = rbf_w[t];
    if (t < NH)      b_s[t] = rbf_b[t];
    for (int i = t; i < MAXD * NH; i += 256) emb_s[i] = dist_emb[i];
    __syncthreads();

    const float step  = 20.0f / 31.0f;
    const float coeff = -0.5f / (step * step);
    size_t base = (size_t)bq * NN;

    int k = t * 2;
    float dd0 = d3[base + k],     dd1 = d3[base + k + 1];
    int   di0 = dm[base + k],     di1 = dm[base + k + 1];
    di0 = min(max(di0, 0), MAXD - 1);
    di1 = min(max(di1, 0), MAXD - 1);

    float r0[NG], r1[NG];
    #pragma unroll
    for (int gg = 0; gg < NG; gg++) {
        float c  = (float)gg * step;
        float f0 = dd0 - c, f1 = dd1 - c;
        r0[gg] = __expf(coeff * f0 * f0);
        r1[gg] = __expf(coeff * f1 * f1);
    }
    #pragma unroll
    for (int h = 0; h < NH; h++) {
        float a0 = b_s[h] + emb_s[di0 * NH + h];
        float a1 = b_s[h] + emb_s[di1 * NH + h];
        #pragma unroll
        for (int gg = 0; gg < NG; gg++) {
            float w = w_s[h * NG + gg];
            a0 += r0[gg] * w;
            a1 += r1[gg] * w;
        }
        size_t idx = ((size_t)(b * NH + h) * NN + q) * NN + k;
        *(__half2*)&bias[idx] = __floats2half2_rn(a0, a1);
    }
}

// ---------------------------------------------------------------------------
// Flash attention (fp32 math, __half bias): block = (q-tile 64, head, batch)
// ---------------------------------------------------------------------------
__global__ void attn_kernel(const float* __restrict__ qkv,
                            const __half* __restrict__ bias,
                            float* __restrict__ ctx) {
    const int qt = blockIdx.x;   // 0..7
    const int h  = blockIdx.y;   // 0..7
    const int b  = blockIdx.z;   // 0..15
    const int q0 = qt * 64;
    const int t  = threadIdx.x;

    __shared__ float Qs[64][33];
    __shared__ float Ks[64][33];
    __shared__ float Vs[64][32];
    __shared__ float S [64][65];
    __shared__ float m_row[64], l_row[64], f_row[64];

    const int d  = t & 31;
    const int iw = t >> 5;
    const int lane = t & 31;

    #pragma unroll
    for (int j = 0; j < 8; j++) {
        int i = iw + j * 8;
        Qs[i][d] = qkv[(size_t)(b * NN + q0 + i) * 768 + h * HD + d];
    }
    if (t < 64) { m_row[t] = -1e30f; l_row[t] = 0.f; f_row[t] = 0.f; }

    const int si = (t >> 4) * 4;
    const int sj = (t & 15) * 4;
    const int qp = (t >> 4) * 4;
    const int d2 = (t & 15) * 2;
    float acc[4][2] = {};
    const float scale = 0.17677669529663687f; // 1/sqrt(32)

    for (int kt = 0; kt < 8; kt++) {
        int k0 = kt * 64;
        __syncthreads();
        #pragma unroll
        for (int j = 0; j < 8; j++) {
            int i = iw + j * 8;
            size_t base = (size_t)(b * NN + k0 + i) * 768 + h * HD + d;
            Ks[i][d] = qkv[base + 256];
            Vs[i][d] = qkv[base + 512];
        }
        __syncthreads();

        float s4[4][4] = {};
        #pragma unroll
        for (int dd = 0; dd < 32; dd++) {
            float a0 = Qs[si + 0][dd], a1 = Qs[si + 1][dd];
            float a2 = Qs[si + 2][dd], a3 = Qs[si + 3][dd];
            float b0 = Ks[sj + 0][dd], b1 = Ks[sj + 1][dd];
            float b2 = Ks[sj + 2][dd], b3 = Ks[sj + 3][dd];
            s4[0][0] += a0 * b0; s4[0][1] += a0 * b1; s4[0][2] += a0 * b2; s4[0][3] += a0 * b3;
            s4[1][0] += a1 * b0; s4[1][1] += a1 * b1; s4[1][2] += a1 * b2; s4[1][3] += a1 * b3;
            s4[2][0] += a2 * b0; s4[2][1] += a2 * b1; s4[2][2] += a2 * b2; s4[2][3] += a2 * b3;
            s4[3][0] += a3 * b0; s4[3][1] += a3 * b1; s4[3][2] += a3 * b2; s4[3][3] += a3 * b3;
        }
        #pragma unroll
        for (int r = 0; r < 4; r++) {
            const __half2* bp = (const __half2*)&bias[
                ((size_t)(b * NH + h) * NN + (q0 + si + r)) * NN + k0 + sj];
            float2 f01 = __half22float2(bp[0]);
            float2 f23 = __half22float2(bp[1]);
            S[si + r][sj + 0] = s4[r][0] * scale + f01.x;
            S[si + r][sj + 1] = s4[r][1] * scale + f01.y;
            S[si + r][sj + 2] = s4[r][2] * scale + f23.x;
            S[si + r][sj + 3] = s4[r][3] * scale + f23.y;
        }
        __syncthreads();

        #pragma unroll
        for (int rr = 0; rr < 8; rr++) {
            int row = iw * 8 + rr;
            float v0 = S[row][lane * 2], v1 = S[row][lane * 2 + 1];
            float mx = fmaxf(v0, v1);
            #pragma unroll
            for (int off = 16; off; off >>= 1)
                mx = fmaxf(mx, __shfl_xor_sync(0xffffffffu, mx, off));
            float mo = m_row[row];
            float mn = fmaxf(mo, mx);
            float p0 = __expf(v0 - mn), p1 = __expf(v1 - mn);
            S[row][lane * 2] = p0; S[row][lane * 2 + 1] = p1;
            float ls = p0 + p1;
            #pragma unroll
            for (int off = 16; off; off >>= 1)
                ls += __shfl_xor_sync(0xffffffffu, ls, off);
            if (lane == 0) {
                float f = __expf(mo - mn);
                m_row[row] = mn;
                l_row[row] = l_row[row] * f + ls;
                f_row[row] = f;
            }
        }
        __syncthreads();

        #pragma unroll
        for (int r = 0; r < 4; r++) {
            float f = f_row[qp + r];
            acc[r][0] *= f; acc[r][1] *= f;
        }
        for (int k = 0; k < 64; k++) {
            float2 vv = *(const float2*)&Vs[k][d2];
            #pragma unroll
            for (int r = 0; r < 4; r++) {
                float p = S[qp + r][k];
                acc[r][0] += p * vv.x;
                acc[r][1] += p * vv.y;
            }
        }
    }

    #pragma unroll
    for (int r = 0; r < 4; r++) {
        int row = qp + r;
        float inv = 1.0f / l_row[row];
        float2 o;
        o.x = acc[r][0] * inv;
        o.y = acc[r][1] * inv;
        *(float2*)&ctx[(size_t)(b * NN + q0 + row) * DIM + h * HD + d2] = o;
    }
}

// ---------------------------------------------------------------------------
// TF32 tensor-core GEMM: C[M,Nn] = A[M,K] @ Bw[Nn,K]^T + bias (+gelu)(+res)
// Block tile 128x128x32, 256 threads (8 warps 2x4), warp tile 64x32,
// mma.m16n8k8.tf32, cp.async double buffered.
// smem row stride 36 floats (=144B, 16B aligned, conflict-free fragments).
// ---------------------------------------------------------------------------
#define GSTRIDE 36
#define GTILE   (128 * GSTRIDE)

template<bool GELU, bool RES>
__global__ __launch_bounds__(256, 2)
void tf32_gemm(const float* __restrict__ A,
               const float* __restrict__ Bw,
               const float* __restrict__ bias,
               const float* __restrict__ res,
               float* __restrict__ C,
               int Nn, int K) {
    extern __shared__ float smem[];
    float* As = smem;               // [2][128][36]
    float* Bs = smem + 2 * GTILE;   // [2][128][36]

    const int t    = threadIdx.x;
    const int bm   = blockIdx.x * 128;
    const int bn   = blockIdx.y * 128;
    const int wid  = t >> 5;
    const int lane = t & 31;
    const int wm   = (wid >> 2) * 64;   // 0 or 64
    const int wn   = (wid & 3) * 32;    // 0,32,64,96
    const int g    = lane >> 2;         // 0..7
    const int tt   = lane & 3;          // 0..3

    // global loader mapping: 256 threads x 4 rows, 16B per row-segment
    const int lrow = t >> 3;            // 0..31
    const int lc4  = (t & 7) * 4;       // 0..28

    float acc[4][4][4];
    #pragma unroll
    for (int i = 0; i < 4; i++)
        #pragma unroll
        for (int j = 0; j < 4; j++)
            #pragma unroll
            for (int c = 0; c < 4; c++) acc[i][j][c] = 0.f;

    const int niter = K >> 5;

    // prologue: stage 0
    {
        #pragma unroll
        for (int i = 0; i < 4; i++) {
            int row = lrow + i * 32;
            cp16(&As[row * GSTRIDE + lc4], &A[(size_t)(bm + row) * K + lc4]);
            cp16(&Bs[row * GSTRIDE + lc4], &Bw[(size_t)(bn + row) * K + lc4]);
        }
        CP_COMMIT();
    }

    for (int it = 0; it < niter; it++) {
        if (it + 1 < niter) {
            int buf = (it + 1) & 1;
            int k0  = (it + 1) * 32;
            #pragma unroll
            for (int i = 0; i < 4; i++) {
                int row = lrow + i * 32;
                cp16(&As[buf * GTILE + row * GSTRIDE + lc4], &A[(size_t)(bm + row) * K + k0 + lc4]);
                cp16(&Bs[buf * GTILE + row * GSTRIDE + lc4], &Bw[(size_t)(bn + row) * K + k0 + lc4]);
            }
            CP_COMMIT();
            asm volatile("cp.async.wait_group 1;");
        } else {
            asm volatile("cp.async.wait_group 0;");
        }
        __syncthreads();

        const float* Ab = As + (it & 1) * GTILE;
        const float* Bb = Bs + (it & 1) * GTILE;

        #pragma unroll
        for (int s = 0; s < 4; s++) {
            int c = s * 8 + tt;
            uint32_t af[4][4];
            #pragma unroll
            for (int mt = 0; mt < 4; mt++) {
                int r0 = wm + mt * 16 + g;
                af[mt][0] = f2tf32(Ab[(r0    ) * GSTRIDE + c    ]);
                af[mt][1] = f2tf32(Ab[(r0 + 8) * GSTRIDE + c    ]);
                af[mt][2] = f2tf32(Ab[(r0    ) * GSTRIDE + c + 4]);
                af[mt][3] = f2tf32(Ab[(r0 + 8) * GSTRIDE + c + 4]);
            }
            uint32_t bf[4][2];
            #pragma unroll
            for (int nt = 0; nt < 4; nt++) {
                int n0 = wn + nt * 8 + g;
                bf[nt][0] = f2tf32(Bb[n0 * GSTRIDE + c    ]);
                bf[nt][1] = f2tf32(Bb[n0 * GSTRIDE + c + 4]);
            }
            #pragma unroll
            for (int mt = 0; mt < 4; mt++)
                #pragma unroll
                for (int nt = 0; nt < 4; nt++)
                    mma_tf32(acc[mt][nt][0], acc[mt][nt][1], acc[mt][nt][2], acc[mt][nt][3],
                             af[mt][0], af[mt][1], af[mt][2], af[mt][3],
                             bf[nt][0], bf[nt][1]);
        }
        __syncthreads();
    }

    // epilogue: c0:(g, 2tt) c1:(g, 2tt+1) c2:(g+8, 2tt) c3:(g+8, 2tt+1)
    #pragma unroll
    for (int mt = 0; mt < 4; mt++) {
        #pragma unroll
        for (int nt = 0; nt < 4; nt++) {
            int row0 = bm + wm + mt * 16 + g;
            int col  = bn + wn + nt * 8 + 2 * tt;
            float b0 = bias[col], b1 = bias[col + 1];

            float v00 = acc[mt][nt][0] + b0;
            float v01 = acc[mt][nt][1] + b1;
            float v10 = acc[mt][nt][2] + b0;
            float v11 = acc[mt][nt][3] + b1;
            if (GELU) {
                v00 = 0.5f * v00 * (1.0f + erff(v00 * 0.70710678118654752f));
                v01 = 0.5f * v01 * (1.0f + erff(v01 * 0.70710678118654752f));
                v10 = 0.5f * v10 * (1.0f + erff(v10 * 0.70710678118654752f));
                v11 = 0.5f * v11 * (1.0f + erff(v11 * 0.70710678118654752f));
            }
            if (RES) {
                float2 r0 = *(const float2*)&res[(size_t)row0 * Nn + col];
                float2 r1 = *(const float2*)&res[(size_t)(row0 + 8) * Nn + col];
                v00 += r0.x; v01 += r0.y;
                v10 += r1.x; v11 += r1.y;
            }
            float2 o0; o0.x = v00; o0.y = v01;
            float2 o1; o1.x = v10; o1.y = v11;
            *(float2*)&C[(size_t)row0 * Nn + col]       = o0;
            *(float2*)&C[(size_t)(row0 + 8) * Nn + col] = o1;
        }
    }
}

#define GEMM_SMEM (4 * GTILE * sizeof(float))   // 73728 B

// ---------------------------------------------------------------------------
// launch
// ---------------------------------------------------------------------------
extern "C" void kernel_launch(void* const* d_in, const int* in_sizes, int n_in,
                              void* d_out, int out_size) {
    const float* x    = (const float*)d_in[0];
    const int*   dm   = (const int*)  d_in[2];
    const float* d3   = (const float*)d_in[3];
    const float* n1g  = (const float*)d_in[4];
    const float* n1b  = (const float*)d_in[5];
    const float* ipw  = (const float*)d_in[6];
    const float* ipb  = (const float*)d_in[7];
    const float* opw  = (const float*)d_in[8];
    const float* opb  = (const float*)d_in[9];
    const float* demb = (const float*)d_in[10];
    const float* rbfw = (const float*)d_in[11];
    const float* rbfb = (const float*)d_in[12];
    const float* n2g  = (const float*)d_in[13];
    const float* n2b  = (const float*)d_in[14];
    const float* w1   = (const float*)d_in[15];
    const float* b1   = (const float*)d_in[16];
    const float* w2   = (const float*)d_in[17];
    const float* b2   = (const float*)d_in[18];
    float* out = (float*)d_out;

    float* scratch = nullptr;
    cudaGetSymbolAddress((void**)&scratch, g_scratch);
    __half* bias = (__half*)(scratch + OFF_BIAS);
    float* hs   = scratch + OFF_H;
    float* qkv  = scratch + OFF_QKV;
    float* ctx  = scratch + OFF_CTX;
    float* hatt = scratch + OFF_HATT;
    float* h2   = scratch + OFF_H2;
    float* f1   = scratch + OFF_F1;

    static bool attr_done = false;
    if (!attr_done) {
        cudaFuncSetAttribute(tf32_gemm<false, false>, cudaFuncAttributeMaxDynamicSharedMemorySize, GEMM_SMEM);
        cudaFuncSetAttribute(tf32_gemm<false, true >, cudaFuncAttributeMaxDynamicSharedMemorySize, GEMM_SMEM);
        cudaFuncSetAttribute(tf32_gemm<true,  false>, cudaFuncAttributeMaxDynamicSharedMemorySize, GEMM_SMEM);
        attr_done = true;
    }

    // 1. h = LN1(x)
    ln_kernel<<<ROWS, 256>>>(x, n1g, n1b, hs);
    // 2. qkv = h @ in_proj_w^T + b
    tf32_gemm<false, false><<<dim3(ROWS / 128, 768 / 128), 256, GEMM_SMEM>>>(hs, ipw, ipb, nullptr, qkv, 768, 256);
    // 3. bias[b,h,q,k] (half)
    bias_kernel<<<ROWS, 256>>>(dm, d3, demb, rbfw, rbfb, bias);
    // 4. attention -> ctx [B,N,DIM]
    attn_kernel<<<dim3(NN / 64, NH, BB), 256>>>(qkv, bias, ctx);
    // 5. hatt = ctx @ out_proj^T + b + h
    tf32_gemm<false, true><<<dim3(ROWS / 128, 256 / 128), 256, GEMM_SMEM>>>(ctx, opw, opb, hs, hatt, 256, 256);
    // 6. h2 = LN2(hatt)
    ln_kernel<<<ROWS, 256>>>(hatt, n2g, n2b, h2);
    // 7. f1 = gelu(h2 @ w1^T + b1)
    tf32_gemm<true, false><<<dim3(ROWS / 128, 1024 / 128), 256, GEMM_SMEM>>>(h2, w1, b1, nullptr, f1, 1024, 256);
    // 8. out = f1 @ w2^T + b2 + hatt
    tf32_gemm<false, true><<<dim3(ROWS / 128, 256 / 128), 256, GEMM_SMEM>>>(f1, w2, b2, hatt, out, 256, 1024);
}